// round 5
// baseline (speedup 1.0000x reference)
#include <cuda_runtime.h>
#include <cstdint>

// Problem dims
#define BB 32
#define SS 64
#define TT 48
#define TM 47      // T-1 decoder steps
#define VV 32000
#define EE 512
#define HH 1024
#define H3 3072
#define H2 2048

#define KC 128          // k-chunk per partial block
#define NSPLIT 8        // k-splits (HH / KC)
#define ENC_G 256       // 32 bundles x 8 ksplits
#define DEC_G 512       // 2 sides x 256
#define PARTSZ ((size_t)BB * H3)

// ---------------- scratch (device global, no allocs) ----------------
#define OFF_EMBS   0ull                                   // B*S*E
#define OFF_GI0    (OFF_EMBS   + (size_t)BB*SS*EE)        // [t][b][n] slabs
#define OFF_H0SEQ  (OFF_GI0    + (size_t)BB*SS*H3)        // [b][t][h]
#define OFF_GI1    (OFF_H0SEQ  + (size_t)BB*SS*HH)        // [t][b][n]
#define OFF_ENCOUT (OFF_GI1    + (size_t)BB*SS*H3)        // [b][t][h]
#define OFF_PROJ   (OFF_ENCOUT + (size_t)BB*SS*HH)        // [b][s][h]
#define OFF_EMBT   (OFF_PROJ   + (size_t)BB*SS*HH)        // rows m=t*B+b
#define OFF_EPRE   (OFF_EMBT   + (size_t)TM*BB*EE)        // [t][b][n] slabs
#define OFF_CAT    (OFF_EPRE   + (size_t)TM*BB*H3)        // rows m=t*B+b, [d1|ctx]
#define OFF_H0A    (OFF_CAT    + (size_t)TM*BB*H2)        // state [k][b]
#define OFF_H0B    (OFF_H0A    + (size_t)BB*HH)
#define OFF_H1A    (OFF_H0B    + (size_t)BB*HH)
#define OFF_H1B    (OFF_H1A    + (size_t)BB*HH)
#define OFF_CTXT   (OFF_H1B    + (size_t)BB*HH)           // ctx [k][b]
#define OFF_D1ROW  (OFF_CTXT   + (size_t)BB*HH)           // d1 [b][h]
#define OFF_PART   (OFF_D1ROW  + (size_t)BB*HH)           // 16 partial slabs [b][n]
#define OFF_CNT    (OFF_PART   + 16*PARTSZ)               // 64 ints (as floats)
#define OFF_WT     (OFF_CNT    + 64)                      // 6 transposed weights [k][n]
#define WT_SZ      ((size_t)HH * H3)
#define SCRATCH_TOTAL (OFF_WT + 6*WT_SZ)

__device__ float g_scratch[SCRATCH_TOTAL];

// ---------------- grid barrier ----------------
__device__ unsigned g_count = 0;
__device__ volatile unsigned g_gen_v = 0;

__device__ __forceinline__ void gbar(unsigned G) {
    __syncthreads();
    if (threadIdx.x == 0) {
        unsigned gen = g_gen_v;
        __threadfence();
        unsigned old = atomicAdd(&g_count, 1u);
        if (old == G - 1u) {
            g_count = 0u;
            __threadfence();
            g_gen_v = gen + 1u;
        } else {
            while (g_gen_v == gen) {}
            __threadfence();
        }
    }
    __syncthreads();
}

// ---------------- small helpers ----------------
__device__ __forceinline__ float4 ld4(const float* p) {
    return *reinterpret_cast<const float4*>(p);
}
__device__ __forceinline__ void st4(float* p, float4 v) {
    *reinterpret_cast<float4*>(p) = v;
}
__device__ __forceinline__ float4 add4(float4 a, float4 b) {
    return make_float4(a.x + b.x, a.y + b.y, a.z + b.z, a.w + b.w);
}

__global__ void zero_kernel(float* p, int n) {
    int i = blockIdx.x * blockDim.x + threadIdx.x;
    if (i < n) p[i] = 0.f;
}

__global__ void embed_enc_kernel(const int* __restrict__ ids,
                                 const float* __restrict__ table,
                                 float* __restrict__ out) {
    int i = blockIdx.x * blockDim.x + threadIdx.x;
    if (i >= BB * SS * EE) return;
    int tok = i / EE;
    int e = i % EE;
    out[i] = table[(size_t)ids[tok] * EE + e];
}

__global__ void embed_dec_kernel(const int* __restrict__ tgt,
                                 const float* __restrict__ table,
                                 float* __restrict__ out) {
    int i = blockIdx.x * blockDim.x + threadIdx.x;
    if (i >= TM * BB * EE) return;
    int m = i / EE;
    int e = i % EE;
    int t = m / BB;
    int b = m % BB;
    out[i] = table[(size_t)tgt[b * TT + t] * EE + e];
}

// weight transpose: Wt[k][n] = W[n][koff + k]
__global__ void transpose_w(const float* __restrict__ W, int ldw, int koff,
                            float* __restrict__ Wt) {
    __shared__ float s[32][33];
    int n0 = blockIdx.x * 32, k0 = blockIdx.y * 32;
    int tx = threadIdx.x & 31, ty = threadIdx.x >> 5;
#pragma unroll
    for (int i = 0; i < 4; i++)
        s[ty + i * 8][tx] = W[(size_t)(n0 + ty + i * 8) * ldw + koff + k0 + tx];
    __syncthreads();
#pragma unroll
    for (int i = 0; i < 4; i++)
        Wt[(size_t)(k0 + ty + i * 8) * H3 + n0 + tx] = s[tx][ty + i * 8];
}

// ---------------- tf32 tensor-core GEMM ----------------
__device__ __forceinline__ uint32_t f2tf(float f) {
    uint32_t u;
    asm("cvt.rna.tf32.f32 %0, %1;" : "=r"(u) : "f"(f));
    return u;
}

#define MODE_NORM 0
#define MODE_PERM 1   // m = t*32+b -> out row b*TM + t   (final logits)
#define MODE_TENC 2   // m = b*64+t -> [t][b][n] slabs
#define MODE_TDEC 3   // m = t*32+b -> [t][b][n] slabs

template <int MODE>
__global__ void __launch_bounds__(256)
gemm_tf32(const float* __restrict__ A, int lda,
          const float* __restrict__ W, int ldw,
          const float* __restrict__ bias,
          float* __restrict__ C, int M, int N, int K) {
    __shared__ uint32_t As[32][132];   // [k][m]
    __shared__ uint32_t Ws[32][132];   // [k][n]
    const int bm = blockIdx.y * 128, bn = blockIdx.x * 128;
    const int tid = threadIdx.x;
    const int warp = tid >> 5, lane = tid & 31;
    const int wm = (warp & 1) * 64, wn = (warp >> 1) * 32;
    const int g = lane >> 2, tig = lane & 3;

    float acc[4][4][4];
#pragma unroll
    for (int a = 0; a < 4; a++)
#pragma unroll
        for (int b = 0; b < 4; b++)
#pragma unroll
            for (int c = 0; c < 4; c++) acc[a][b][c] = 0.f;

    float4 pa[4], pw[4];
#pragma unroll
    for (int i = 0; i < 4; i++) {
        int e = tid + i * 256;
        int m = e >> 3, kq = (e & 7) * 4;
        float4 v = make_float4(0.f, 0.f, 0.f, 0.f);
        if (bm + m < M) v = ld4(A + (size_t)(bm + m) * lda + kq);
        pa[i] = v;
        pw[i] = ld4(W + (size_t)(bn + m) * ldw + kq);
    }
#pragma unroll
    for (int i = 0; i < 4; i++) {
        int e = tid + i * 256;
        int m = e >> 3, kq = (e & 7) * 4;
        As[kq + 0][m] = f2tf(pa[i].x); As[kq + 1][m] = f2tf(pa[i].y);
        As[kq + 2][m] = f2tf(pa[i].z); As[kq + 3][m] = f2tf(pa[i].w);
        Ws[kq + 0][m] = f2tf(pw[i].x); Ws[kq + 1][m] = f2tf(pw[i].y);
        Ws[kq + 2][m] = f2tf(pw[i].z); Ws[kq + 3][m] = f2tf(pw[i].w);
    }
    __syncthreads();

    for (int k0 = 0; k0 < K; k0 += 32) {
        bool has_next = (k0 + 32) < K;
        if (has_next) {
#pragma unroll
            for (int i = 0; i < 4; i++) {
                int e = tid + i * 256;
                int m = e >> 3, kq = (e & 7) * 4;
                float4 v = make_float4(0.f, 0.f, 0.f, 0.f);
                if (bm + m < M) v = ld4(A + (size_t)(bm + m) * lda + k0 + 32 + kq);
                pa[i] = v;
                pw[i] = ld4(W + (size_t)(bn + m) * ldw + k0 + 32 + kq);
            }
        }
#pragma unroll
        for (int kk = 0; kk < 32; kk += 8) {
            uint32_t af[4][4];
#pragma unroll
            for (int mt = 0; mt < 4; mt++) {
                int ml = wm + mt * 16 + g;
                af[mt][0] = As[kk + tig][ml];
                af[mt][1] = As[kk + tig][ml + 8];
                af[mt][2] = As[kk + tig + 4][ml];
                af[mt][3] = As[kk + tig + 4][ml + 8];
            }
            uint32_t bf[4][2];
#pragma unroll
            for (int nt = 0; nt < 4; nt++) {
                int nl = wn + nt * 8 + g;
                bf[nt][0] = Ws[kk + tig][nl];
                bf[nt][1] = Ws[kk + tig + 4][nl];
            }
#pragma unroll
            for (int mt = 0; mt < 4; mt++)
#pragma unroll
                for (int nt = 0; nt < 4; nt++) {
                    asm volatile(
                        "mma.sync.aligned.m16n8k8.row.col.f32.tf32.tf32.f32 "
                        "{%0,%1,%2,%3}, {%4,%5,%6,%7}, {%8,%9}, {%0,%1,%2,%3};\n"
                        : "+f"(acc[mt][nt][0]), "+f"(acc[mt][nt][1]),
                          "+f"(acc[mt][nt][2]), "+f"(acc[mt][nt][3])
                        : "r"(af[mt][0]), "r"(af[mt][1]), "r"(af[mt][2]), "r"(af[mt][3]),
                          "r"(bf[nt][0]), "r"(bf[nt][1]));
                }
        }
        __syncthreads();
        if (has_next) {
#pragma unroll
            for (int i = 0; i < 4; i++) {
                int e = tid + i * 256;
                int m = e >> 3, kq = (e & 7) * 4;
                As[kq + 0][m] = f2tf(pa[i].x); As[kq + 1][m] = f2tf(pa[i].y);
                As[kq + 2][m] = f2tf(pa[i].z); As[kq + 3][m] = f2tf(pa[i].w);
                Ws[kq + 0][m] = f2tf(pw[i].x); Ws[kq + 1][m] = f2tf(pw[i].y);
                Ws[kq + 2][m] = f2tf(pw[i].z); Ws[kq + 3][m] = f2tf(pw[i].w);
            }
            __syncthreads();
        }
    }

#pragma unroll
    for (int mt = 0; mt < 4; mt++) {
#pragma unroll
        for (int i2 = 0; i2 < 2; i2++) {
            int m = bm + wm + mt * 16 + g + i2 * 8;
            if (m >= M) continue;
#pragma unroll
            for (int nt = 0; nt < 4; nt++) {
#pragma unroll
                for (int j = 0; j < 2; j++) {
                    int n = bn + wn + nt * 8 + tig * 2 + j;
                    float v = acc[mt][nt][i2 * 2 + j];
                    if (bias) v += bias[n];
                    if (MODE == MODE_NORM) {
                        C[(size_t)m * N + n] = v;
                    } else if (MODE == MODE_PERM) {
                        int b = m & 31, t = m >> 5;
                        C[(size_t)(b * TM + t) * N + n] = v;
                    } else if (MODE == MODE_TENC) {
                        int t = m & 63, b = m >> 6;
                        C[((size_t)t * 32 + b) * N + n] = v;
                    } else {  // MODE_TDEC
                        int t = m >> 5, b = m & 31;
                        C[((size_t)t * 32 + b) * N + n] = v;
                    }
                }
            }
        }
    }
}

// ---------------- recurrent partial: 32 cols x 3 gates over a KC k-chunk ----------------
// A [k][b] (stride 32), Wt [k][n] (stride H3). Writes slab [b][n].
__device__ __forceinline__ void rec_partial(
    const float* __restrict__ A, const float* __restrict__ Wt,
    float* __restrict__ slab, float* sA, int tid, int c0, int k0) {
    const float4* src = reinterpret_cast<const float4*>(A + (size_t)k0 * 32);
#pragma unroll
    for (int i = 0; i < 4; i++)
        reinterpret_cast<float4*>(sA)[tid + i * 256] = src[tid + i * 256];
    __syncthreads();
    const int cc = c0 + (tid & 7) * 4;
    const int b = tid >> 3;
    float4 a0 = make_float4(0.f, 0.f, 0.f, 0.f);
    float4 a1 = a0, a2 = a0;
    const float* wp = Wt + (size_t)k0 * H3 + cc;
#pragma unroll 4
    for (int k = 0; k < KC; k++) {
        float a = sA[k * 32 + b];
        float4 w0 = ld4(wp + (size_t)k * H3);
        float4 w1 = ld4(wp + (size_t)k * H3 + HH);
        float4 w2 = ld4(wp + (size_t)k * H3 + 2 * HH);
        a0.x += a * w0.x; a0.y += a * w0.y; a0.z += a * w0.z; a0.w += a * w0.w;
        a1.x += a * w1.x; a1.y += a * w1.y; a1.z += a * w1.z; a1.w += a * w1.w;
        a2.x += a * w2.x; a2.y += a * w2.y; a2.z += a * w2.z; a2.w += a * w2.w;
    }
    float* P = slab + (size_t)b * H3 + cc;
    st4(P, a0);
    st4(P + HH, a1);
    st4(P + 2 * HH, a2);
}

// ---------------- fused gate for a 32-col bundle (winner block) ----------------
__device__ __forceinline__ void gate_bundle(
    int tid, int c0, const float* __restrict__ part, bool has_x,
    const float* __restrict__ gi_slab,   // [b][n] or null
    const float* __restrict__ gi_vec,    // or null
    const float* __restrict__ bhh,
    const float* __restrict__ hc, float* __restrict__ hnout,  // [k][b]
    float* __restrict__ seq_base, int t,  // if: seq_base[(b*SS+t)*HH + h]
    float* __restrict__ cat_t,            // if: cat_t[b*H2 + h]
    float* __restrict__ d1) {             // if: d1[b*HH + h]
    const int b = tid & 31;
    const int h = c0 + (tid >> 5) * 4;
    float4 hr = ld4(bhh + h);
    float4 hz = ld4(bhh + HH + h);
    float4 hn = ld4(bhh + 2 * HH + h);
#pragma unroll
    for (int j = 0; j < NSPLIT; j++) {
        const float* P = part + (size_t)j * PARTSZ + (size_t)b * H3 + h;
        hr = add4(hr, ld4(P));
        hz = add4(hz, ld4(P + HH));
        hn = add4(hn, ld4(P + 2 * HH));
    }
    float4 gr = make_float4(0.f, 0.f, 0.f, 0.f);
    float4 gz = gr, gn = gr;
    if (gi_slab) {
        const float* G = gi_slab + (size_t)b * H3 + h;
        gr = ld4(G);
        gz = ld4(G + HH);
        gn = ld4(G + 2 * HH);
    }
    if (gi_vec) {
        gr = add4(gr, ld4(gi_vec + h));
        gz = add4(gz, ld4(gi_vec + HH + h));
        gn = add4(gn, ld4(gi_vec + 2 * HH + h));
    }
    if (has_x) {
#pragma unroll
        for (int j = NSPLIT; j < 2 * NSPLIT; j++) {
            const float* P = part + (size_t)j * PARTSZ + (size_t)b * H3 + h;
            gr = add4(gr, ld4(P));
            gz = add4(gz, ld4(P + HH));
            gn = add4(gn, ld4(P + 2 * HH));
        }
    }
    float grr[4] = {gr.x, gr.y, gr.z, gr.w};
    float gzz[4] = {gz.x, gz.y, gz.z, gz.w};
    float gnn[4] = {gn.x, gn.y, gn.z, gn.w};
    float hrr[4] = {hr.x, hr.y, hr.z, hr.w};
    float hzz[4] = {hz.x, hz.y, hz.z, hz.w};
    float hnn[4] = {hn.x, hn.y, hn.z, hn.w};
#pragma unroll
    for (int i = 0; i < 4; i++) {
        float r = 1.f / (1.f + expf(-(grr[i] + hrr[i])));
        float z = 1.f / (1.f + expf(-(gzz[i] + hzz[i])));
        float n = tanhf(gnn[i] + r * hnn[i]);
        float hp = hc[(size_t)(h + i) * 32 + b];
        float out = (1.f - z) * n + z * hp;
        hnout[(size_t)(h + i) * 32 + b] = out;
        if (seq_base) seq_base[((size_t)b * SS + t) * HH + h + i] = out;
        if (cat_t) cat_t[(size_t)b * H2 + h + i] = out;
        if (d1) d1[(size_t)b * HH + h + i] = out;
    }
}

// ---------------- persistent encoder scan (one GRU layer, SS steps) ----------------
__global__ void __launch_bounds__(256, 4)
enc_scan(const float* __restrict__ gi,   // [t][b][n]
         const float* __restrict__ wt,   // [k][n]
         const float* __restrict__ bhh,
         float* hA, float* hB,
         float* __restrict__ seq,        // [b][t][h]
         float* __restrict__ d1row,      // null or written at last step
         float* __restrict__ part, int* __restrict__ cnt) {
    __shared__ float sA[KC * 32];
    __shared__ int s_win;
    const int tid = threadIdx.x;
    const int nb = blockIdx.x & 31;
    const int ks = blockIdx.x >> 5;
    const int c0 = nb * 32;
    const int k0 = ks * KC;
    if (blockIdx.x == 0)
        for (int i = tid; i < 64; i += 256) cnt[i] = 0;
    gbar(ENC_G);
    float* hc = hA;
    float* hn = hB;
    for (int t = 0; t < SS; t++) {
        rec_partial(hc, wt, part + (size_t)ks * PARTSZ, sA, tid, c0, k0);
        __syncthreads();
        if (tid == 0) {
            __threadfence();
            int old = atomicAdd(&cnt[nb], 1);
            s_win = (old == (t + 1) * NSPLIT - 1);
            if (s_win) __threadfence();
        }
        __syncthreads();
        if (s_win)
            gate_bundle(tid, c0, part, false,
                        gi + (size_t)t * BB * H3, nullptr, bhh,
                        hc, hn, seq, t, nullptr,
                        (t == SS - 1) ? d1row : nullptr);
        gbar(ENC_G);
        float* tp = hc; hc = hn; hn = tp;
    }
}

// ---------------- persistent decoder scan ----------------
__global__ void __launch_bounds__(256, 4)
dec_scan(const float* __restrict__ proj, const float* __restrict__ encout,
         const int* __restrict__ src_ids,
         const float* __restrict__ epre,  // [t][b][n]
         float* __restrict__ cat, float* __restrict__ ctxt, float* __restrict__ d1row,
         float* h0A, float* h0B, float* h1A, float* h1B,
         const float* __restrict__ w_hh0, const float* __restrict__ w_ih0c,
         const float* __restrict__ w_hh1, const float* __restrict__ w_ih1,
         const float* __restrict__ bhh0, const float* __restrict__ bih1,
         const float* __restrict__ bhh1,
         float* __restrict__ part, int* __restrict__ cnt) {
    __shared__ float sA[KC * 32];
    __shared__ float sSc[SS];
    __shared__ int s_win;
    const int tid = threadIdx.x;
    const int bid = blockIdx.x;
    const int side = bid >> 8;     // 0: h-side, 1: x-side
    const int lb = bid & 255;
    const int nb = lb & 31;
    const int ks = lb >> 5;
    const int c0 = nb * 32;
    const int k0 = ks * KC;
    if (bid == 0)
        for (int i = tid; i < 64; i += 256) cnt[i] = 0;
    gbar(DEC_G);
    float* hc0 = h0A; float* hn0 = h0B;
    float* hc1 = h1A; float* hn1 = h1B;
    for (int t = 0; t < TM; t++) {
        float* cat_t = cat + (size_t)t * BB * H2;
        // ---- attention (blocks 0..31) ----
        if (bid < BB) {
            const int b = bid;
            const int lane = tid & 31, warp = tid >> 5;
            const float* d1b = d1row + (size_t)b * HH;
            for (int s = warp; s < SS; s += 8) {
                const float* pr = proj + ((size_t)b * SS + s) * HH;
                float p = 0.f;
#pragma unroll
                for (int j = 0; j < 8; j++) {
                    int kk = j * 128 + lane * 4;
                    float4 dv = ld4(d1b + kk);
                    float4 pv = ld4(pr + kk);
                    p += dv.x * pv.x + dv.y * pv.y + dv.z * pv.z + dv.w * pv.w;
                }
#pragma unroll
                for (int o = 16; o; o >>= 1) p += __shfl_xor_sync(0xffffffffu, p, o);
                if (lane == 0) sSc[s] = (src_ids[b * SS + s] != 0) ? p : -1e9f;
            }
            __syncthreads();
            if (warp == 0) {
                float v0 = sSc[lane], v1 = sSc[lane + 32];
                float m = fmaxf(v0, v1);
#pragma unroll
                for (int o = 16; o; o >>= 1) m = fmaxf(m, __shfl_xor_sync(0xffffffffu, m, o));
                float e0 = expf(v0 - m), e1 = expf(v1 - m);
                float su = e0 + e1;
#pragma unroll
                for (int o = 16; o; o >>= 1) su += __shfl_xor_sync(0xffffffffu, su, o);
                sSc[lane] = e0 / su;
                sSc[lane + 32] = e1 / su;
            }
            __syncthreads();
            for (int h = tid; h < HH; h += 256) {
                const float* eb = encout + (size_t)b * SS * HH + h;
                float a = 0.f;
#pragma unroll 8
                for (int s = 0; s < SS; s++) a += sSc[s] * eb[(size_t)s * HH];
                ctxt[(size_t)h * 32 + b] = a;
                cat_t[(size_t)b * H2 + HH + h] = a;
            }
        }
        gbar(DEC_G);
        // ---- layer 0: h-side = h0 @ whh0 ; x-side = ctx @ wih0[:,E:] ----
        rec_partial(side ? ctxt : hc0, side ? w_ih0c : w_hh0,
                    part + (size_t)(side * NSPLIT + ks) * PARTSZ, sA, tid, c0, k0);
        __syncthreads();
        if (tid == 0) {
            __threadfence();
            int old = atomicAdd(&cnt[nb], 1);
            s_win = (old == (t + 1) * 2 * NSPLIT - 1);
            if (s_win) __threadfence();
        }
        __syncthreads();
        if (s_win)
            gate_bundle(tid, c0, part, true,
                        epre + (size_t)t * BB * H3, nullptr, bhh0,
                        hc0, hn0, nullptr, t, nullptr, nullptr);
        gbar(DEC_G);
        // ---- layer 1: h-side = h1 @ whh1 ; x-side = h0_new @ wih1 ----
        rec_partial(side ? hn0 : hc1, side ? w_ih1 : w_hh1,
                    part + (size_t)(side * NSPLIT + ks) * PARTSZ, sA, tid, c0, k0);
        __syncthreads();
        if (tid == 0) {
            __threadfence();
            int old = atomicAdd(&cnt[32 + nb], 1);
            s_win = (old == (t + 1) * 2 * NSPLIT - 1);
            if (s_win) __threadfence();
        }
        __syncthreads();
        if (s_win)
            gate_bundle(tid, c0, part, true,
                        nullptr, bih1, bhh1,
                        hc1, hn1, nullptr, t, cat_t, d1row);
        gbar(DEC_G);
        float* tp;
        tp = hc0; hc0 = hn0; hn0 = tp;
        tp = hc1; hc1 = hn1; hn1 = tp;
    }
}

// ---------------- host launcher ----------------
extern "C" void kernel_launch(void* const* d_in, const int* in_sizes, int n_in,
                              void* d_out, int out_size) {
    const int*   src_ids  = (const int*)d_in[0];
    const int*   tgt_ids  = (const int*)d_in[2];
    const float* enc_emb  = (const float*)d_in[3];
    const float* dec_emb  = (const float*)d_in[4];
    const float* enc_wih0 = (const float*)d_in[5];
    const float* enc_whh0 = (const float*)d_in[6];
    const float* enc_bih0 = (const float*)d_in[7];
    const float* enc_bhh0 = (const float*)d_in[8];
    const float* enc_wih1 = (const float*)d_in[9];
    const float* enc_whh1 = (const float*)d_in[10];
    const float* enc_bih1 = (const float*)d_in[11];
    const float* enc_bhh1 = (const float*)d_in[12];
    const float* dec_wih0 = (const float*)d_in[13];
    const float* dec_whh0 = (const float*)d_in[14];
    const float* dec_bih0 = (const float*)d_in[15];
    const float* dec_bhh0 = (const float*)d_in[16];
    const float* dec_wih1 = (const float*)d_in[17];
    const float* dec_whh1 = (const float*)d_in[18];
    const float* dec_bih1 = (const float*)d_in[19];
    const float* dec_bhh1 = (const float*)d_in[20];
    const float* attn_w   = (const float*)d_in[21];
    const float* out_w    = (const float*)d_in[22];
    const float* out_b    = (const float*)d_in[23];
    float* out = (float*)d_out;

    float* base = nullptr;
    cudaGetSymbolAddress((void**)&base, g_scratch);
    float* embS   = base + OFF_EMBS;
    float* gi0    = base + OFF_GI0;
    float* h0seq  = base + OFF_H0SEQ;
    float* gi1    = base + OFF_GI1;
    float* encout = base + OFF_ENCOUT;
    float* proj   = base + OFF_PROJ;
    float* embT   = base + OFF_EMBT;
    float* epre   = base + OFF_EPRE;
    float* cat    = base + OFF_CAT;
    float* h0A    = base + OFF_H0A;
    float* h0B    = base + OFF_H0B;
    float* h1A    = base + OFF_H1A;
    float* h1B    = base + OFF_H1B;
    float* ctxt   = base + OFF_CTXT;
    float* d1row  = base + OFF_D1ROW;
    float* part   = base + OFF_PART;
    int*   cnt    = (int*)(base + OFF_CNT);
    float* wt_ewhh0  = base + OFF_WT + 0 * WT_SZ;
    float* wt_ewhh1  = base + OFF_WT + 1 * WT_SZ;
    float* wt_dwhh0  = base + OFF_WT + 2 * WT_SZ;
    float* wt_dwhh1  = base + OFF_WT + 3 * WT_SZ;
    float* wt_dwih0c = base + OFF_WT + 4 * WT_SZ;
    float* wt_dwih1  = base + OFF_WT + 5 * WT_SZ;

    dim3 tgrid(H3 / 32, HH / 32);
    transpose_w<<<tgrid, 256>>>(enc_whh0, HH, 0, wt_ewhh0);
    transpose_w<<<tgrid, 256>>>(enc_whh1, HH, 0, wt_ewhh1);
    transpose_w<<<tgrid, 256>>>(dec_whh0, HH, 0, wt_dwhh0);
    transpose_w<<<tgrid, 256>>>(dec_whh1, HH, 0, wt_dwhh1);
    transpose_w<<<tgrid, 256>>>(dec_wih0, EE + HH, EE, wt_dwih0c);
    transpose_w<<<tgrid, 256>>>(dec_wih1, HH, 0, wt_dwih1);

    // ---- encoder ----
    embed_enc_kernel<<<(BB * SS * EE + 255) / 256, 256>>>(src_ids, enc_emb, embS);
    gemm_tf32<MODE_TENC><<<dim3(H3 / 128, 16), 256>>>(
        embS, EE, enc_wih0, EE, enc_bih0, gi0, BB * SS, H3, EE);
    zero_kernel<<<(4 * BB * HH + 255) / 256, 256>>>(h0A, 4 * BB * HH);

    enc_scan<<<ENC_G, 256>>>(gi0, wt_ewhh0, enc_bhh0, h0A, h0B, h0seq, nullptr, part, cnt);
    gemm_tf32<MODE_TENC><<<dim3(H3 / 128, 16), 256>>>(
        h0seq, HH, enc_wih1, HH, enc_bih1, gi1, BB * SS, H3, HH);
    enc_scan<<<ENC_G, 256>>>(gi1, wt_ewhh1, enc_bhh1, h1A, h1B, encout, d1row, part, cnt);

    gemm_tf32<MODE_NORM><<<dim3(HH / 128, 16), 256>>>(
        encout, HH, attn_w, HH, nullptr, proj, BB * SS, HH, HH);

    // ---- decoder pre ----
    embed_dec_kernel<<<(TM * BB * EE + 255) / 256, 256>>>(tgt_ids, dec_emb, embT);
    gemm_tf32<MODE_TDEC><<<dim3(H3 / 128, (TM * BB + 127) / 128), 256>>>(
        embT, EE, dec_wih0, EE + HH, dec_bih0, epre, TM * BB, H3, EE);

    // ---- decoder scan (persistent) ----
    dec_scan<<<DEC_G, 256>>>(proj, encout, src_ids, epre, cat, ctxt, d1row,
                             h0A, h0B, h1A, h1B,
                             wt_dwhh0, wt_dwih0c, wt_dwhh1, wt_dwih1,
                             dec_bhh0, dec_bih1, dec_bhh1, part, cnt);

    // ---- final projection ----
    gemm_tf32<MODE_PERM><<<dim3(VV / 128, (TM * BB + 127) / 128), 256>>>(
        cat, H2, out_w, H2, out_b, out, TM * BB, VV, H2);
}